// round 9
// baseline (speedup 1.0000x reference)
#include <cuda_runtime.h>
#include <cstdint>

// ---------------------------------------------------------------------------
// EmbedderMessageFunction (TGN message): fused gather + time-encode +
// MLP(512 -> relu 512 -> 256), TF32 mma.sync (m16n8k8), M-tile = 64 events.
// R9: build/GEMM1 interleave (k-range scheduling) + copy-free B double buffer.
// ---------------------------------------------------------------------------

#define E_TILE   64
#define THREADS  256

// smem layout (bytes)
#define OFF_A     0            // A fragment region: 4 mt * 64 ks * 32 lanes * 16B
#define OFF_SA    131072       // staging A: 64 x 136 floats = 34816
#define OFF_SB    165888       // staging B: 64 x 136 floats = 34816
#define OFF_B1    200704       // 512 floats
#define OFF_B2    202752       // 256 floats
#define OFF_FREQ  203776       // 128 floats
#define OFF_PHASE 204288       // 128 floats
#define OFF_DT    204800       // 64 floats
#define OFF_SRC   205056       // 64 ints
#define OFF_DST   205312
#define OFF_EID   205568
#define SMEM_BYTES 205824

#define STAG_PITCH 136         // floats; 544B rows keep 16B cp.async alignment

// fragment-major tf32 weights (built once per launch by prep kernel)
// W1F: [ntg 0..63][ks 0..63][lane 0..31][2]   (HIDDEN=512 -> 64 n-tiles)
// W2F: [ntg 0..31][ks 0..63][lane 0..31][2]   (OUT=256    -> 32 n-tiles)
__device__ float g_W1F[64 * 64 * 32 * 2];
__device__ float g_W2F[32 * 64 * 32 * 2];

static __device__ __forceinline__ uint32_t f2tf32(float x) {
    uint32_t r;
    asm("cvt.rna.tf32.f32 %0, %1;" : "=r"(r) : "f"(x));
    return r;
}

static __device__ __forceinline__ uint32_t smem_u32(const void* p) {
    uint32_t a;
    asm("{ .reg .u64 t; cvta.to.shared.u64 t, %1; cvt.u32.u64 %0, t; }"
        : "=r"(a) : "l"(p));
    return a;
}

static __device__ __forceinline__ void cp16(uint32_t dst, const void* src) {
    asm volatile("cp.async.cg.shared.global [%0], [%1], 16;"
                 :: "r"(dst), "l"(src) : "memory");
}
#define CP_COMMIT() asm volatile("cp.async.commit_group;" ::: "memory")
#define CP_WAIT(n)  asm volatile("cp.async.wait_group %0;" :: "n"(n) : "memory")

static __device__ __forceinline__ void mma8(float* d, uint4 a, float2 b) {
    asm volatile(
        "mma.sync.aligned.m16n8k8.row.col.f32.tf32.tf32.f32 "
        "{%0,%1,%2,%3}, {%4,%5,%6,%7}, {%8,%9}, {%0,%1,%2,%3};"
        : "+f"(d[0]), "+f"(d[1]), "+f"(d[2]), "+f"(d[3])
        : "r"(a.x), "r"(a.y), "r"(a.z), "r"(a.w),
          "r"(__float_as_uint(b.x)), "r"(__float_as_uint(b.y)));
}

// ---------------------------- prep kernel ----------------------------------
// B fragment layout for mma.m16n8k8.row.col:
//   b0: (row = lane%4,     col = lane/4)  of the 8x8 k-by-n tile
//   b1: (row = lane%4 + 4, col = lane/4)

__global__ void prep_weights_kernel(const float* __restrict__ W1,
                                    const float* __restrict__ W2) {
    int t0 = blockIdx.x * blockDim.x + threadIdx.x;
    int stride = gridDim.x * blockDim.x;
    for (int t = t0; t < 64 * 64 * 32; t += stride) {
        int lane = t & 31, ks = (t >> 5) & 63, ntg = t >> 11;
        int r = lane & 3, cg = lane >> 2;
        int k0 = ks * 8, n = ntg * 8 + cg;
        g_W1F[2 * t]     = __uint_as_float(f2tf32(W1[(size_t)(k0 + r) * 512 + n]));
        g_W1F[2 * t + 1] = __uint_as_float(f2tf32(W1[(size_t)(k0 + r + 4) * 512 + n]));
    }
    for (int t = t0; t < 32 * 64 * 32; t += stride) {
        int lane = t & 31, ks = (t >> 5) & 63, ntg = t >> 11;
        int r = lane & 3, cg = lane >> 2;
        int k0 = ks * 8, n = ntg * 8 + cg;
        g_W2F[2 * t]     = __uint_as_float(f2tf32(W2[(size_t)(k0 + r) * 256 + n]));
        g_W2F[2 * t + 1] = __uint_as_float(f2tf32(W2[(size_t)(k0 + r + 4) * 256 + n]));
    }
}

// ----------------------------- main kernel ---------------------------------

__global__ __launch_bounds__(THREADS, 1)
void tgn_msg_kernel(const int*   __restrict__ src_nodes,
                    const int*   __restrict__ dst_nodes,
                    const float* __restrict__ timestamps,
                    const int*   __restrict__ event_indices,
                    const int*   __restrict__ nidx,
                    const float* __restrict__ node_emb,
                    const float* __restrict__ last_update,
                    const float* __restrict__ feats,
                    const float* __restrict__ freq,
                    const float* __restrict__ phase,
                    const float* __restrict__ b1,
                    const float* __restrict__ b2,
                    float*       __restrict__ out,
                    int E) {
    extern __shared__ char smem[];
    float* sA    = (float*)(smem + OFF_A);
    float* stagA = (float*)(smem + OFF_SA);
    float* stagB = (float*)(smem + OFF_SB);
    float* s_b1  = (float*)(smem + OFF_B1);
    float* s_b2  = (float*)(smem + OFF_B2);
    float* s_frq = (float*)(smem + OFF_FREQ);
    float* s_phs = (float*)(smem + OFF_PHASE);
    float* s_dt  = (float*)(smem + OFF_DT);
    int*   s_src = (int*)(smem + OFF_SRC);
    int*   s_dst = (int*)(smem + OFF_DST);
    int*   s_eid = (int*)(smem + OFF_EID);

    const uint32_t sbA = smem_u32(stagA);
    const uint32_t sbB = smem_u32(stagB);

    const int tid  = threadIdx.x;
    const int warp = tid >> 5;
    const int lane = tid & 31;
    const int gid  = lane >> 2;   // group id (row within fragment)
    const int tig  = lane & 3;    // thread in group

    const int base = blockIdx.x * E_TILE;

    // ---- preamble: indices / scalars into smem ----
    if (tid < E_TILE) {
        int e = base + tid;
        if (e >= E) e = E - 1;
        s_src[tid] = src_nodes[e];
        s_dst[tid] = dst_nodes[e];
        s_eid[tid] = event_indices[e];
        s_dt[tid]  = timestamps[e] - last_update[nidx[e]];
    }
    if (tid < 128) { s_frq[tid] = freq[tid]; s_phs[tid] = phase[tid]; }
    for (int i = tid; i < 512; i += THREADS) s_b1[i] = b1[i];
    if (tid < 256) s_b2[tid] = b2[tid];
    __syncthreads();

    // ---- async gather issue: src -> stagA (G0), dst -> stagB (G1) ----
    #pragma unroll
    for (int i = 0; i < 8; i++) {
        int lin = i * 256 + tid;
        int row = lin >> 5;
        int q   = lin & 31;
        cp16(sbA + (row * STAG_PITCH + q * 4) * 4,
             node_emb + (size_t)s_src[row] * 128 + q * 4);
    }
    CP_COMMIT();   // G0
    #pragma unroll
    for (int i = 0; i < 8; i++) {
        int lin = i * 256 + tid;
        int row = lin >> 5;
        int q   = lin & 31;
        cp16(sbB + (row * STAG_PITCH + q * 4) * 4,
             node_emb + (size_t)s_dst[row] * 128 + q * 4);
    }
    CP_COMMIT();   // G1

    // ---- chunk 2 (time encoding): compute cos directly in fragment layout ----
    #pragma unroll
    for (int i = 0; i < 8; i++) {
        int f   = i * 8 + warp;
        int mt  = f >> 4;
        int ksl = f & 15;
        int ra = mt * 16 + gid;
        int ca = ksl * 8 + tig;
        float dt0 = s_dt[ra], dt1 = s_dt[ra + 8];
        float f0 = s_frq[ca], f4 = s_frq[ca + 4];
        float p0 = s_phs[ca], p4 = s_phs[ca + 4];
        uint4 u;
        u.x = f2tf32(cosf(__fmaf_rn(dt0, f0, p0)));
        u.y = f2tf32(cosf(__fmaf_rn(dt1, f0, p0)));
        u.z = f2tf32(cosf(__fmaf_rn(dt0, f4, p4)));
        u.w = f2tf32(cosf(__fmaf_rn(dt1, f4, p4)));
        *(uint4*)(sA + ((mt * 64 + 32 + ksl) * 32 + lane) * 4) = u;
    }

    // ---- repack helper (reads staging, rounds to tf32, writes fragments) ----
    auto repack = [&](float* stag, int chunk) {
        #pragma unroll
        for (int i = 0; i < 8; i++) {
            int f   = i * 8 + warp;
            int mt  = f >> 4;
            int ksl = f & 15;
            int ra = mt * 16 + gid;
            int ca = ksl * 8 + tig;
            uint4 u;
            u.x = f2tf32(stag[ra * STAG_PITCH + ca]);
            u.y = f2tf32(stag[(ra + 8) * STAG_PITCH + ca]);
            u.z = f2tf32(stag[ra * STAG_PITCH + ca + 4]);
            u.w = f2tf32(stag[(ra + 8) * STAG_PITCH + ca + 4]);
            *(uint4*)(sA + ((mt * 64 + chunk * 16 + ksl) * 32 + lane) * 4) = u;
        }
    };

    // ---- GEMM1 accumulators (kept live across interleaved k-ranges) ----
    float acc[4][8][4];
    #pragma unroll
    for (int mt = 0; mt < 4; mt++)
        #pragma unroll
        for (int nt = 0; nt < 8; nt++)
            #pragma unroll
            for (int r = 0; r < 4; r++) acc[mt][nt][r] = 0.0f;

    const float* bbase1 = g_W1F + (size_t)(warp * 8) * 4096;

    // GEMM1 over one 16-wide k-range; copy-free distance-2 B double buffer.
    auto g1range = [&](int k0) {
        float2 b0[8], b1f[8];
        #pragma unroll
        for (int nt = 0; nt < 8; nt++) {
            b0[nt]  = *(const float2*)(bbase1 + (nt * 64 + k0) * 64 + lane * 2);
            b1f[nt] = *(const float2*)(bbase1 + (nt * 64 + k0 + 1) * 64 + lane * 2);
        }
        #pragma unroll
        for (int kk = 0; kk < 16; kk += 2) {
            int ks = k0 + kk;
            uint4 a0[4], a1[4];
            #pragma unroll
            for (int mt = 0; mt < 4; mt++) {
                a0[mt] = *(const uint4*)(sA + ((mt * 64 + ks) * 32 + lane) * 4);
                a1[mt] = *(const uint4*)(sA + ((mt * 64 + ks + 1) * 32 + lane) * 4);
            }
            #pragma unroll
            for (int mt = 0; mt < 4; mt++)
                #pragma unroll
                for (int nt = 0; nt < 8; nt++)
                    mma8(acc[mt][nt], a0[mt], b0[nt]);
            if (kk < 14) {
                #pragma unroll
                for (int nt = 0; nt < 8; nt++)
                    b0[nt] = *(const float2*)(bbase1 + (nt * 64 + ks + 2) * 64 + lane * 2);
            }
            #pragma unroll
            for (int mt = 0; mt < 4; mt++)
                #pragma unroll
                for (int nt = 0; nt < 8; nt++)
                    mma8(acc[mt][nt], a1[mt], b1f[nt]);
            if (kk < 14) {
                #pragma unroll
                for (int nt = 0; nt < 8; nt++)
                    b1f[nt] = *(const float2*)(bbase1 + (nt * 64 + ks + 3) * 64 + lane * 2);
            }
        }
    };

    // ---- interleaved schedule: repacks between MMA k-ranges ----
    CP_WAIT(1);          // G0 (src) landed
    __syncthreads();
    repack(stagA, 0);    // src -> chunk 0
    __syncthreads();     // stagA free

    // feats -> stagA (G2), in flight during first MMA ranges
    #pragma unroll
    for (int i = 0; i < 8; i++) {
        int lin = i * 256 + tid;
        int row = lin >> 5;
        int q   = lin & 31;
        cp16(sbA + (row * STAG_PITCH + q * 4) * 4,
             feats + (size_t)s_eid[row] * 128 + q * 4);
    }
    CP_COMMIT();   // G2

    g1range(0);          // chunk 0 (src)   while G1/G2 fly
    g1range(32);         // chunk 2 (cos)

    CP_WAIT(1);          // G1 (dst) landed
    __syncthreads();
    repack(stagB, 1);    // dst -> chunk 1
    __syncthreads();
    g1range(16);         // chunk 1 (dst)

    CP_WAIT(0);          // G2 (feats) landed
    __syncthreads();
    repack(stagA, 3);    // feats -> chunk 3
    __syncthreads();
    g1range(48);         // chunk 3 (feats)

    // ---- relu + b1, write h back into A region (fragment-major) ----
    __syncthreads();   // everyone done reading msg A
    #pragma unroll
    for (int mt = 0; mt < 4; mt++) {
        #pragma unroll
        for (int nt = 0; nt < 8; nt++) {
            #pragma unroll
            for (int cr = 0; cr < 4; cr++) {
                int row = mt * 16 + gid + 8 * (cr >> 1);
                int n   = warp * 64 + nt * 8 + 2 * tig + (cr & 1);
                float v = fmaxf(acc[mt][nt][cr] + s_b1[n], 0.0f);
                int r15 = row & 15;
                int ks  = n >> 3;
                int c0  = n & 7;
                int l2  = (r15 & 7) * 4 + (c0 & 3);
                int rg  = (r15 >> 3) + 2 * (c0 >> 2);
                sA[((mt * 64 + ks) * 32 + l2) * 4 + rg] =
                    __uint_as_float(f2tf32(v));
            }
        }
    }
    __syncthreads();

    // ---- GEMM2: out[64x256] = h @ W2 ; N-slice 32 per warp ----
    float acc2[4][4][4];
    #pragma unroll
    for (int mt = 0; mt < 4; mt++)
        #pragma unroll
        for (int nt = 0; nt < 4; nt++)
            #pragma unroll
            for (int r = 0; r < 4; r++) acc2[mt][nt][r] = 0.0f;

    {
        const float* bbase = g_W2F + (size_t)(warp * 4) * 4096;
        float2 b0[4], b1f[4];
        #pragma unroll
        for (int nt = 0; nt < 4; nt++) {
            b0[nt]  = *(const float2*)(bbase + (nt * 64 + 0) * 64 + lane * 2);
            b1f[nt] = *(const float2*)(bbase + (nt * 64 + 1) * 64 + lane * 2);
        }
        #pragma unroll
        for (int ks = 0; ks < 64; ks += 2) {
            uint4 a0[4], a1[4];
            #pragma unroll
            for (int mt = 0; mt < 4; mt++) {
                a0[mt] = *(const uint4*)(sA + ((mt * 64 + ks) * 32 + lane) * 4);
                a1[mt] = *(const uint4*)(sA + ((mt * 64 + ks + 1) * 32 + lane) * 4);
            }
            #pragma unroll
            for (int mt = 0; mt < 4; mt++)
                #pragma unroll
                for (int nt = 0; nt < 4; nt++)
                    mma8(acc2[mt][nt], a0[mt], b0[nt]);
            if (ks < 62) {
                #pragma unroll
                for (int nt = 0; nt < 4; nt++)
                    b0[nt] = *(const float2*)(bbase + (nt * 64 + ks + 2) * 64 + lane * 2);
            }
            #pragma unroll
            for (int mt = 0; mt < 4; mt++)
                #pragma unroll
                for (int nt = 0; nt < 4; nt++)
                    mma8(acc2[mt][nt], a1[mt], b1f[nt]);
            if (ks < 62) {
                #pragma unroll
                for (int nt = 0; nt < 4; nt++)
                    b1f[nt] = *(const float2*)(bbase + (nt * 64 + ks + 3) * 64 + lane * 2);
            }
        }
    }

    // ---- epilogue: + b2, store ----
    #pragma unroll
    for (int mt = 0; mt < 4; mt++) {
        #pragma unroll
        for (int nt = 0; nt < 4; nt++) {
            int n  = warp * 32 + nt * 8 + 2 * tig;
            float bx = s_b2[n], by = s_b2[n + 1];
            int r0 = mt * 16 + gid;
            int e0 = base + r0;
            if (e0 < E) {
                float2 o;
                o.x = acc2[mt][nt][0] + bx;
                o.y = acc2[mt][nt][1] + by;
                *(float2*)(out + (size_t)e0 * 256 + n) = o;
            }
            int e1 = base + r0 + 8;
            if (e1 < E) {
                float2 o;
                o.x = acc2[mt][nt][2] + bx;
                o.y = acc2[mt][nt][3] + by;
                *(float2*)(out + (size_t)e1 * 256 + n) = o;
            }
        }
    }
}

// ------------------------------- launch ------------------------------------

extern "C" void kernel_launch(void* const* d_in, const int* in_sizes, int n_in,
                              void* d_out, int out_size) {
    const int*   src_nodes     = (const int*)d_in[0];
    const int*   dst_nodes     = (const int*)d_in[1];
    const float* timestamps    = (const float*)d_in[2];
    const int*   event_indices = (const int*)d_in[3];
    const int*   nidx          = (const int*)d_in[4];
    const float* node_emb      = (const float*)d_in[5];
    const float* last_update   = (const float*)d_in[6];
    const float* feats         = (const float*)d_in[7];
    const float* freq          = (const float*)d_in[8];
    const float* phase         = (const float*)d_in[9];
    const float* W1            = (const float*)d_in[10];
    const float* b1v           = (const float*)d_in[11];
    const float* W2            = (const float*)d_in[12];
    const float* b2v           = (const float*)d_in[13];
    float* out = (float*)d_out;

    int E = in_sizes[0];

    cudaFuncSetAttribute(tgn_msg_kernel,
                         cudaFuncAttributeMaxDynamicSharedMemorySize, SMEM_BYTES);

    prep_weights_kernel<<<128, 256>>>(W1, W2);

    int nblk = (E + E_TILE - 1) / E_TILE;
    tgn_msg_kernel<<<nblk, THREADS, SMEM_BYTES>>>(
        src_nodes, dst_nodes, timestamps, event_indices, nidx,
        node_emb, last_update, feats, freq, phase, b1v, b2v, out, E);
}

// round 12
// speedup vs baseline: 1.0024x; 1.0024x over previous
#include <cuda_runtime.h>
#include <cstdint>

// ---------------------------------------------------------------------------
// EmbedderMessageFunction (TGN message): fused gather + time-encode +
// MLP(512 -> relu 512 -> 256), TF32 mma.sync (m16n8k8), M-tile = 64 events.
// R10: R9's build/GEMM1 interleaved schedule + R8's register-lean loop bodies.
// ---------------------------------------------------------------------------

#define E_TILE   64
#define THREADS  256

// smem layout (bytes)
#define OFF_A     0            // A fragment region: 4 mt * 64 ks * 32 lanes * 16B
#define OFF_SA    131072       // staging A: 64 x 136 floats = 34816
#define OFF_SB    165888       // staging B: 64 x 136 floats = 34816
#define OFF_B1    200704       // 512 floats
#define OFF_B2    202752       // 256 floats
#define OFF_FREQ  203776       // 128 floats
#define OFF_PHASE 204288       // 128 floats
#define OFF_DT    204800       // 64 floats
#define OFF_SRC   205056       // 64 ints
#define OFF_DST   205312
#define OFF_EID   205568
#define SMEM_BYTES 205824

#define STAG_PITCH 136         // floats; 544B rows keep 16B cp.async alignment

// fragment-major tf32 weights (built once per launch by prep kernel)
// W1F: [ntg 0..63][ks 0..63][lane 0..31][2]   (HIDDEN=512 -> 64 n-tiles)
// W2F: [ntg 0..31][ks 0..63][lane 0..31][2]   (OUT=256    -> 32 n-tiles)
__device__ float g_W1F[64 * 64 * 32 * 2];
__device__ float g_W2F[32 * 64 * 32 * 2];

static __device__ __forceinline__ uint32_t f2tf32(float x) {
    uint32_t r;
    asm("cvt.rna.tf32.f32 %0, %1;" : "=r"(r) : "f"(x));
    return r;
}

static __device__ __forceinline__ uint32_t smem_u32(const void* p) {
    uint32_t a;
    asm("{ .reg .u64 t; cvta.to.shared.u64 t, %1; cvt.u32.u64 %0, t; }"
        : "=r"(a) : "l"(p));
    return a;
}

static __device__ __forceinline__ void cp16(uint32_t dst, const void* src) {
    asm volatile("cp.async.cg.shared.global [%0], [%1], 16;"
                 :: "r"(dst), "l"(src) : "memory");
}
#define CP_COMMIT() asm volatile("cp.async.commit_group;" ::: "memory")
#define CP_WAIT(n)  asm volatile("cp.async.wait_group %0;" :: "n"(n) : "memory")

static __device__ __forceinline__ void mma8(float* d, uint4 a, float2 b) {
    asm volatile(
        "mma.sync.aligned.m16n8k8.row.col.f32.tf32.tf32.f32 "
        "{%0,%1,%2,%3}, {%4,%5,%6,%7}, {%8,%9}, {%0,%1,%2,%3};"
        : "+f"(d[0]), "+f"(d[1]), "+f"(d[2]), "+f"(d[3])
        : "r"(a.x), "r"(a.y), "r"(a.z), "r"(a.w),
          "r"(__float_as_uint(b.x)), "r"(__float_as_uint(b.y)));
}

// ---------------------------- prep kernel ----------------------------------
// B fragment layout for mma.m16n8k8.row.col:
//   b0: (row = lane%4,     col = lane/4)  of the 8x8 k-by-n tile
//   b1: (row = lane%4 + 4, col = lane/4)

__global__ void prep_weights_kernel(const float* __restrict__ W1,
                                    const float* __restrict__ W2) {
    int t0 = blockIdx.x * blockDim.x + threadIdx.x;
    int stride = gridDim.x * blockDim.x;
    for (int t = t0; t < 64 * 64 * 32; t += stride) {
        int lane = t & 31, ks = (t >> 5) & 63, ntg = t >> 11;
        int r = lane & 3, cg = lane >> 2;
        int k0 = ks * 8, n = ntg * 8 + cg;
        g_W1F[2 * t]     = __uint_as_float(f2tf32(W1[(size_t)(k0 + r) * 512 + n]));
        g_W1F[2 * t + 1] = __uint_as_float(f2tf32(W1[(size_t)(k0 + r + 4) * 512 + n]));
    }
    for (int t = t0; t < 32 * 64 * 32; t += stride) {
        int lane = t & 31, ks = (t >> 5) & 63, ntg = t >> 11;
        int r = lane & 3, cg = lane >> 2;
        int k0 = ks * 8, n = ntg * 8 + cg;
        g_W2F[2 * t]     = __uint_as_float(f2tf32(W2[(size_t)(k0 + r) * 256 + n]));
        g_W2F[2 * t + 1] = __uint_as_float(f2tf32(W2[(size_t)(k0 + r + 4) * 256 + n]));
    }
}

// ----------------------------- main kernel ---------------------------------

__global__ __launch_bounds__(THREADS, 1)
void tgn_msg_kernel(const int*   __restrict__ src_nodes,
                    const int*   __restrict__ dst_nodes,
                    const float* __restrict__ timestamps,
                    const int*   __restrict__ event_indices,
                    const int*   __restrict__ nidx,
                    const float* __restrict__ node_emb,
                    const float* __restrict__ last_update,
                    const float* __restrict__ feats,
                    const float* __restrict__ freq,
                    const float* __restrict__ phase,
                    const float* __restrict__ b1,
                    const float* __restrict__ b2,
                    float*       __restrict__ out,
                    int E) {
    extern __shared__ char smem[];
    float* sA    = (float*)(smem + OFF_A);
    float* stagA = (float*)(smem + OFF_SA);
    float* stagB = (float*)(smem + OFF_SB);
    float* s_b1  = (float*)(smem + OFF_B1);
    float* s_b2  = (float*)(smem + OFF_B2);
    float* s_frq = (float*)(smem + OFF_FREQ);
    float* s_phs = (float*)(smem + OFF_PHASE);
    float* s_dt  = (float*)(smem + OFF_DT);
    int*   s_src = (int*)(smem + OFF_SRC);
    int*   s_dst = (int*)(smem + OFF_DST);
    int*   s_eid = (int*)(smem + OFF_EID);

    const uint32_t sbA = smem_u32(stagA);
    const uint32_t sbB = smem_u32(stagB);

    const int tid  = threadIdx.x;
    const int warp = tid >> 5;
    const int lane = tid & 31;
    const int gid  = lane >> 2;   // group id (row within fragment)
    const int tig  = lane & 3;    // thread in group

    const int base = blockIdx.x * E_TILE;

    // ---- preamble: indices / scalars into smem ----
    if (tid < E_TILE) {
        int e = base + tid;
        if (e >= E) e = E - 1;
        s_src[tid] = src_nodes[e];
        s_dst[tid] = dst_nodes[e];
        s_eid[tid] = event_indices[e];
        s_dt[tid]  = timestamps[e] - last_update[nidx[e]];
    }
    if (tid < 128) { s_frq[tid] = freq[tid]; s_phs[tid] = phase[tid]; }
    for (int i = tid; i < 512; i += THREADS) s_b1[i] = b1[i];
    if (tid < 256) s_b2[tid] = b2[tid];
    __syncthreads();

    // ---- async gather issue: src -> stagA (G0), dst -> stagB (G1) ----
    #pragma unroll
    for (int i = 0; i < 8; i++) {
        int lin = i * 256 + tid;
        int row = lin >> 5;
        int q   = lin & 31;
        cp16(sbA + (row * STAG_PITCH + q * 4) * 4,
             node_emb + (size_t)s_src[row] * 128 + q * 4);
    }
    CP_COMMIT();   // G0
    #pragma unroll
    for (int i = 0; i < 8; i++) {
        int lin = i * 256 + tid;
        int row = lin >> 5;
        int q   = lin & 31;
        cp16(sbB + (row * STAG_PITCH + q * 4) * 4,
             node_emb + (size_t)s_dst[row] * 128 + q * 4);
    }
    CP_COMMIT();   // G1

    // ---- chunk 2 (time encoding): compute cos directly in fragment layout ----
    #pragma unroll
    for (int i = 0; i < 8; i++) {
        int f   = i * 8 + warp;
        int mt  = f >> 4;
        int ksl = f & 15;
        int ra = mt * 16 + gid;
        int ca = ksl * 8 + tig;
        float dt0 = s_dt[ra], dt1 = s_dt[ra + 8];
        float f0 = s_frq[ca], f4 = s_frq[ca + 4];
        float p0 = s_phs[ca], p4 = s_phs[ca + 4];
        uint4 u;
        u.x = f2tf32(cosf(__fmaf_rn(dt0, f0, p0)));
        u.y = f2tf32(cosf(__fmaf_rn(dt1, f0, p0)));
        u.z = f2tf32(cosf(__fmaf_rn(dt0, f4, p4)));
        u.w = f2tf32(cosf(__fmaf_rn(dt1, f4, p4)));
        *(uint4*)(sA + ((mt * 64 + 32 + ksl) * 32 + lane) * 4) = u;
    }

    // ---- repack helper (reads staging, rounds to tf32, writes fragments) ----
    auto repack = [&](float* stag, int chunk) {
        #pragma unroll
        for (int i = 0; i < 8; i++) {
            int f   = i * 8 + warp;
            int mt  = f >> 4;
            int ksl = f & 15;
            int ra = mt * 16 + gid;
            int ca = ksl * 8 + tig;
            uint4 u;
            u.x = f2tf32(stag[ra * STAG_PITCH + ca]);
            u.y = f2tf32(stag[(ra + 8) * STAG_PITCH + ca]);
            u.z = f2tf32(stag[ra * STAG_PITCH + ca + 4]);
            u.w = f2tf32(stag[(ra + 8) * STAG_PITCH + ca + 4]);
            *(uint4*)(sA + ((mt * 64 + chunk * 16 + ksl) * 32 + lane) * 4) = u;
        }
    };

    // ---- GEMM1 accumulators (live across interleaved k-ranges) ----
    float acc[4][8][4];
    #pragma unroll
    for (int mt = 0; mt < 4; mt++)
        #pragma unroll
        for (int nt = 0; nt < 8; nt++)
            #pragma unroll
            for (int r = 0; r < 4; r++) acc[mt][nt][r] = 0.0f;

    const float* bbase1 = g_W1F + (size_t)(warp * 8) * 4096;

    // GEMM1 over one 16-wide k-range; R8-style parity buffer + bu copy
    // (register-lean codegen: 230 regs measured in R8).
    auto g1range = [&](int k0) {
        float2 bbuf[2][8];
        #pragma unroll
        for (int nt = 0; nt < 8; nt++) {
            bbuf[0][nt] = *(const float2*)(bbase1 + (nt * 64 + k0) * 64 + lane * 2);
            bbuf[1][nt] = *(const float2*)(bbase1 + (nt * 64 + k0 + 1) * 64 + lane * 2);
        }
        #pragma unroll 2
        for (int kk = 0; kk < 16; kk++) {
            int ks = k0 + kk;
            float2 bu[8];
            #pragma unroll
            for (int nt = 0; nt < 8; nt++) bu[nt] = bbuf[kk & 1][nt];
            if (kk < 14) {
                #pragma unroll
                for (int nt = 0; nt < 8; nt++)
                    bbuf[kk & 1][nt] =
                        *(const float2*)(bbase1 + (nt * 64 + ks + 2) * 64 + lane * 2);
            }
            uint4 a[4];
            #pragma unroll
            for (int mt = 0; mt < 4; mt++)
                a[mt] = *(const uint4*)(sA + ((mt * 64 + ks) * 32 + lane) * 4);
            #pragma unroll
            for (int mt = 0; mt < 4; mt++)
                #pragma unroll
                for (int nt = 0; nt < 8; nt++)
                    mma8(acc[mt][nt], a[mt], bu[nt]);
        }
    };

    // ---- interleaved schedule: repacks between MMA k-ranges ----
    CP_WAIT(1);          // G0 (src) landed
    __syncthreads();
    repack(stagA, 0);    // src -> chunk 0
    __syncthreads();     // stagA free

    // feats -> stagA (G2), in flight during first MMA ranges
    #pragma unroll
    for (int i = 0; i < 8; i++) {
        int lin = i * 256 + tid;
        int row = lin >> 5;
        int q   = lin & 31;
        cp16(sbA + (row * STAG_PITCH + q * 4) * 4,
             feats + (size_t)s_eid[row] * 128 + q * 4);
    }
    CP_COMMIT();   // G2

    g1range(0);          // chunk 0 (src)   while G1/G2 fly
    g1range(32);         // chunk 2 (cos)

    CP_WAIT(1);          // G1 (dst) landed
    __syncthreads();
    repack(stagB, 1);    // dst -> chunk 1
    __syncthreads();
    g1range(16);         // chunk 1 (dst)

    CP_WAIT(0);          // G2 (feats) landed
    __syncthreads();
    repack(stagA, 3);    // feats -> chunk 3
    __syncthreads();
    g1range(48);         // chunk 3 (feats)

    // ---- relu + b1, write h back into A region (fragment-major) ----
    __syncthreads();   // everyone done reading msg A
    #pragma unroll
    for (int mt = 0; mt < 4; mt++) {
        #pragma unroll
        for (int nt = 0; nt < 8; nt++) {
            #pragma unroll
            for (int cr = 0; cr < 4; cr++) {
                int row = mt * 16 + gid + 8 * (cr >> 1);
                int n   = warp * 64 + nt * 8 + 2 * tig + (cr & 1);
                float v = fmaxf(acc[mt][nt][cr] + s_b1[n], 0.0f);
                int r15 = row & 15;
                int ks  = n >> 3;
                int c0  = n & 7;
                int l2  = (r15 & 7) * 4 + (c0 & 3);
                int rg  = (r15 >> 3) + 2 * (c0 >> 2);
                sA[((mt * 64 + ks) * 32 + l2) * 4 + rg] =
                    __uint_as_float(f2tf32(v));
            }
        }
    }
    __syncthreads();

    // ---- GEMM2: out[64x256] = h @ W2 ; N-slice 32 per warp (R8 body) ----
    float acc2[4][4][4];
    #pragma unroll
    for (int mt = 0; mt < 4; mt++)
        #pragma unroll
        for (int nt = 0; nt < 4; nt++)
            #pragma unroll
            for (int r = 0; r < 4; r++) acc2[mt][nt][r] = 0.0f;

    {
        const float* bbase = g_W2F + (size_t)(warp * 4) * 4096;
        float2 bbuf[2][4];
        #pragma unroll
        for (int nt = 0; nt < 4; nt++) {
            bbuf[0][nt] = *(const float2*)(bbase + (nt * 64 + 0) * 64 + lane * 2);
            bbuf[1][nt] = *(const float2*)(bbase + (nt * 64 + 1) * 64 + lane * 2);
        }
        #pragma unroll 2
        for (int ks = 0; ks < 64; ks++) {
            float2 bu[4];
            #pragma unroll
            for (int nt = 0; nt < 4; nt++) bu[nt] = bbuf[ks & 1][nt];
            if (ks < 62) {
                #pragma unroll
                for (int nt = 0; nt < 4; nt++)
                    bbuf[ks & 1][nt] =
                        *(const float2*)(bbase + (nt * 64 + ks + 2) * 64 + lane * 2);
            }
            uint4 a[4];
            #pragma unroll
            for (int mt = 0; mt < 4; mt++)
                a[mt] = *(const uint4*)(sA + ((mt * 64 + ks) * 32 + lane) * 4);
            #pragma unroll
            for (int mt = 0; mt < 4; mt++)
                #pragma unroll
                for (int nt = 0; nt < 4; nt++)
                    mma8(acc2[mt][nt], a[mt], bu[nt]);
        }
    }

    // ---- epilogue: + b2, store ----
    #pragma unroll
    for (int mt = 0; mt < 4; mt++) {
        #pragma unroll
        for (int nt = 0; nt < 4; nt++) {
            int n  = warp * 32 + nt * 8 + 2 * tig;
            float bx = s_b2[n], by = s_b2[n + 1];
            int r0 = mt * 16 + gid;
            int e0 = base + r0;
            if (e0 < E) {
                float2 o;
                o.x = acc2[mt][nt][0] + bx;
                o.y = acc2[mt][nt][1] + by;
                *(float2*)(out + (size_t)e0 * 256 + n) = o;
            }
            int e1 = base + r0 + 8;
            if (e1 < E) {
                float2 o;
                o.x = acc2[mt][nt][2] + bx;
                o.y = acc2[mt][nt][3] + by;
                *(float2*)(out + (size_t)e1 * 256 + n) = o;
            }
        }
    }
}

// ------------------------------- launch ------------------------------------

extern "C" void kernel_launch(void* const* d_in, const int* in_sizes, int n_in,
                              void* d_out, int out_size) {
    const int*   src_nodes     = (const int*)d_in[0];
    const int*   dst_nodes     = (const int*)d_in[1];
    const float* timestamps    = (const float*)d_in[2];
    const int*   event_indices = (const int*)d_in[3];
    const int*   nidx          = (const int*)d_in[4];
    const float* node_emb      = (const float*)d_in[5];
    const float* last_update   = (const float*)d_in[6];
    const float* feats         = (const float*)d_in[7];
    const float* freq          = (const float*)d_in[8];
    const float* phase         = (const float*)d_in[9];
    const float* W1            = (const float*)d_in[10];
    const float* b1v           = (const float*)d_in[11];
    const float* W2            = (const float*)d_in[12];
    const float* b2v           = (const float*)d_in[13];
    float* out = (float*)d_out;

    int E = in_sizes[0];

    cudaFuncSetAttribute(tgn_msg_kernel,
                         cudaFuncAttributeMaxDynamicSharedMemorySize, SMEM_BYTES);

    prep_weights_kernel<<<128, 256>>>(W1, W2);

    int nblk = (E + E_TILE - 1) / E_TILE;
    tgn_msg_kernel<<<nblk, THREADS, SMEM_BYTES>>>(
        src_nodes, dst_nodes, timestamps, event_indices, nidx,
        node_emb, last_update, feats, freq, phase, b1v, b2v, out, E);
}

// round 13
// speedup vs baseline: 1.0502x; 1.0477x over previous
#include <cuda_runtime.h>
#include <cstdint>

// ---------------------------------------------------------------------------
// EmbedderMessageFunction (TGN message): fused gather + time-encode +
// MLP(512 -> relu 512 -> 256), TF32 mma.sync (m16n8k8), M-tile = 64 events.
// R13: R8 monolithic schedule + copy-free 2x-unrolled B double buffer
//      (single reused A fragment; no bu MOV copies, no a0/a1 pairing).
// ---------------------------------------------------------------------------

#define E_TILE   64
#define THREADS  256

// smem layout (bytes)
#define OFF_A     0            // A fragment region: 4 mt * 64 ks * 32 lanes * 16B
#define OFF_SA    131072       // staging A: 64 x 136 floats = 34816
#define OFF_SB    165888       // staging B: 64 x 136 floats = 34816
#define OFF_B1    200704       // 512 floats
#define OFF_B2    202752       // 256 floats
#define OFF_FREQ  203776       // 128 floats
#define OFF_PHASE 204288       // 128 floats
#define OFF_DT    204800       // 64 floats
#define OFF_SRC   205056       // 64 ints
#define OFF_DST   205312
#define OFF_EID   205568
#define SMEM_BYTES 205824

#define STAG_PITCH 136         // floats; 544B rows keep 16B cp.async alignment

// fragment-major tf32 weights (built once per launch by prep kernel)
// W1F: [ntg 0..63][ks 0..63][lane 0..31][2]   (HIDDEN=512 -> 64 n-tiles)
// W2F: [ntg 0..31][ks 0..63][lane 0..31][2]   (OUT=256    -> 32 n-tiles)
__device__ float g_W1F[64 * 64 * 32 * 2];
__device__ float g_W2F[32 * 64 * 32 * 2];

static __device__ __forceinline__ uint32_t f2tf32(float x) {
    uint32_t r;
    asm("cvt.rna.tf32.f32 %0, %1;" : "=r"(r) : "f"(x));
    return r;
}

static __device__ __forceinline__ uint32_t smem_u32(const void* p) {
    uint32_t a;
    asm("{ .reg .u64 t; cvta.to.shared.u64 t, %1; cvt.u32.u64 %0, t; }"
        : "=r"(a) : "l"(p));
    return a;
}

static __device__ __forceinline__ void cp16(uint32_t dst, const void* src) {
    asm volatile("cp.async.cg.shared.global [%0], [%1], 16;"
                 :: "r"(dst), "l"(src) : "memory");
}
#define CP_COMMIT() asm volatile("cp.async.commit_group;" ::: "memory")
#define CP_WAIT(n)  asm volatile("cp.async.wait_group %0;" :: "n"(n) : "memory")

static __device__ __forceinline__ void mma8(float* d, uint4 a, float2 b) {
    asm volatile(
        "mma.sync.aligned.m16n8k8.row.col.f32.tf32.tf32.f32 "
        "{%0,%1,%2,%3}, {%4,%5,%6,%7}, {%8,%9}, {%0,%1,%2,%3};"
        : "+f"(d[0]), "+f"(d[1]), "+f"(d[2]), "+f"(d[3])
        : "r"(a.x), "r"(a.y), "r"(a.z), "r"(a.w),
          "r"(__float_as_uint(b.x)), "r"(__float_as_uint(b.y)));
}

// ---------------------------- prep kernel ----------------------------------
// B fragment layout for mma.m16n8k8.row.col:
//   b0: (row = lane%4,     col = lane/4)  of the 8x8 k-by-n tile
//   b1: (row = lane%4 + 4, col = lane/4)

__global__ void prep_weights_kernel(const float* __restrict__ W1,
                                    const float* __restrict__ W2) {
    int t0 = blockIdx.x * blockDim.x + threadIdx.x;
    int stride = gridDim.x * blockDim.x;
    for (int t = t0; t < 64 * 64 * 32; t += stride) {
        int lane = t & 31, ks = (t >> 5) & 63, ntg = t >> 11;
        int r = lane & 3, cg = lane >> 2;
        int k0 = ks * 8, n = ntg * 8 + cg;
        g_W1F[2 * t]     = __uint_as_float(f2tf32(W1[(size_t)(k0 + r) * 512 + n]));
        g_W1F[2 * t + 1] = __uint_as_float(f2tf32(W1[(size_t)(k0 + r + 4) * 512 + n]));
    }
    for (int t = t0; t < 32 * 64 * 32; t += stride) {
        int lane = t & 31, ks = (t >> 5) & 63, ntg = t >> 11;
        int r = lane & 3, cg = lane >> 2;
        int k0 = ks * 8, n = ntg * 8 + cg;
        g_W2F[2 * t]     = __uint_as_float(f2tf32(W2[(size_t)(k0 + r) * 256 + n]));
        g_W2F[2 * t + 1] = __uint_as_float(f2tf32(W2[(size_t)(k0 + r + 4) * 256 + n]));
    }
}

// ----------------------------- main kernel ---------------------------------

__global__ __launch_bounds__(THREADS, 1)
void tgn_msg_kernel(const int*   __restrict__ src_nodes,
                    const int*   __restrict__ dst_nodes,
                    const float* __restrict__ timestamps,
                    const int*   __restrict__ event_indices,
                    const int*   __restrict__ nidx,
                    const float* __restrict__ node_emb,
                    const float* __restrict__ last_update,
                    const float* __restrict__ feats,
                    const float* __restrict__ freq,
                    const float* __restrict__ phase,
                    const float* __restrict__ b1,
                    const float* __restrict__ b2,
                    float*       __restrict__ out,
                    int E) {
    extern __shared__ char smem[];
    float* sA    = (float*)(smem + OFF_A);
    float* stagA = (float*)(smem + OFF_SA);
    float* stagB = (float*)(smem + OFF_SB);
    float* s_b1  = (float*)(smem + OFF_B1);
    float* s_b2  = (float*)(smem + OFF_B2);
    float* s_frq = (float*)(smem + OFF_FREQ);
    float* s_phs = (float*)(smem + OFF_PHASE);
    float* s_dt  = (float*)(smem + OFF_DT);
    int*   s_src = (int*)(smem + OFF_SRC);
    int*   s_dst = (int*)(smem + OFF_DST);
    int*   s_eid = (int*)(smem + OFF_EID);

    const uint32_t sbA = smem_u32(stagA);
    const uint32_t sbB = smem_u32(stagB);

    const int tid  = threadIdx.x;
    const int warp = tid >> 5;
    const int lane = tid & 31;
    const int gid  = lane >> 2;   // group id (row within fragment)
    const int tig  = lane & 3;    // thread in group

    const int base = blockIdx.x * E_TILE;

    // ---- preamble: indices / scalars into smem ----
    if (tid < E_TILE) {
        int e = base + tid;
        if (e >= E) e = E - 1;
        s_src[tid] = src_nodes[e];
        s_dst[tid] = dst_nodes[e];
        s_eid[tid] = event_indices[e];
        s_dt[tid]  = timestamps[e] - last_update[nidx[e]];
    }
    if (tid < 128) { s_frq[tid] = freq[tid]; s_phs[tid] = phase[tid]; }
    for (int i = tid; i < 512; i += THREADS) s_b1[i] = b1[i];
    if (tid < 256) s_b2[tid] = b2[tid];
    __syncthreads();

    // ---- async gather issue: src -> stagA (G0), dst -> stagB (G1) ----
    #pragma unroll
    for (int i = 0; i < 8; i++) {
        int lin = i * 256 + tid;
        int row = lin >> 5;
        int q   = lin & 31;
        cp16(sbA + (row * STAG_PITCH + q * 4) * 4,
             node_emb + (size_t)s_src[row] * 128 + q * 4);
    }
    CP_COMMIT();   // G0
    #pragma unroll
    for (int i = 0; i < 8; i++) {
        int lin = i * 256 + tid;
        int row = lin >> 5;
        int q   = lin & 31;
        cp16(sbB + (row * STAG_PITCH + q * 4) * 4,
             node_emb + (size_t)s_dst[row] * 128 + q * 4);
    }
    CP_COMMIT();   // G1

    // ---- chunk 2 (time encoding): compute cos directly in fragment layout ----
    #pragma unroll
    for (int i = 0; i < 8; i++) {
        int f   = i * 8 + warp;
        int mt  = f >> 4;
        int ksl = f & 15;
        int ra = mt * 16 + gid;
        int ca = ksl * 8 + tig;
        float dt0 = s_dt[ra], dt1 = s_dt[ra + 8];
        float f0 = s_frq[ca], f4 = s_frq[ca + 4];
        float p0 = s_phs[ca], p4 = s_phs[ca + 4];
        uint4 u;
        u.x = f2tf32(cosf(__fmaf_rn(dt0, f0, p0)));
        u.y = f2tf32(cosf(__fmaf_rn(dt1, f0, p0)));
        u.z = f2tf32(cosf(__fmaf_rn(dt0, f4, p4)));
        u.w = f2tf32(cosf(__fmaf_rn(dt1, f4, p4)));
        *(uint4*)(sA + ((mt * 64 + 32 + ksl) * 32 + lane) * 4) = u;
    }

    // ---- repack helper (reads staging, rounds to tf32, writes fragments) ----
    auto repack = [&](float* stag, int chunk) {
        #pragma unroll
        for (int i = 0; i < 8; i++) {
            int f   = i * 8 + warp;
            int mt  = f >> 4;
            int ksl = f & 15;
            int ra = mt * 16 + gid;
            int ca = ksl * 8 + tig;
            uint4 u;
            u.x = f2tf32(stag[ra * STAG_PITCH + ca]);
            u.y = f2tf32(stag[(ra + 8) * STAG_PITCH + ca]);
            u.z = f2tf32(stag[ra * STAG_PITCH + ca + 4]);
            u.w = f2tf32(stag[(ra + 8) * STAG_PITCH + ca + 4]);
            *(uint4*)(sA + ((mt * 64 + chunk * 16 + ksl) * 32 + lane) * 4) = u;
        }
    };

    CP_WAIT(1);          // G0 (src) landed
    __syncthreads();
    repack(stagA, 0);    // src -> chunk 0
    __syncthreads();     // stagA free

    // ---- feats -> stagA (G2) ----
    #pragma unroll
    for (int i = 0; i < 8; i++) {
        int lin = i * 256 + tid;
        int row = lin >> 5;
        int q   = lin & 31;
        cp16(sbA + (row * STAG_PITCH + q * 4) * 4,
             feats + (size_t)s_eid[row] * 128 + q * 4);
    }
    CP_COMMIT();   // G2

    CP_WAIT(1);          // G1 (dst) landed (G2 may be pending)
    __syncthreads();
    repack(stagB, 1);    // dst -> chunk 1

    CP_WAIT(0);          // G2 (feats) landed
    __syncthreads();
    repack(stagA, 3);    // feats -> chunk 3
    __syncthreads();

    // ---- GEMM1: h[64x512] = msg @ W1 ; N-slice 64 per warp ----
    // Copy-free double buffer: even k uses b0 (reloaded in place for k+2),
    // odd k uses b1f (reloaded for k+3). Single a[4] reused across halves.
    float acc[4][8][4];
    #pragma unroll
    for (int mt = 0; mt < 4; mt++)
        #pragma unroll
        for (int nt = 0; nt < 8; nt++)
            #pragma unroll
            for (int r = 0; r < 4; r++) acc[mt][nt][r] = 0.0f;

    {
        const float* bbase = g_W1F + (size_t)(warp * 8) * 4096;
        float2 b0[8], b1f[8];
        #pragma unroll
        for (int nt = 0; nt < 8; nt++) {
            b0[nt]  = *(const float2*)(bbase + (nt * 64 + 0) * 64 + lane * 2);
            b1f[nt] = *(const float2*)(bbase + (nt * 64 + 1) * 64 + lane * 2);
        }
        #pragma unroll 1
        for (int ks = 0; ks < 64; ks += 2) {
            uint4 a[4];
            // even half
            #pragma unroll
            for (int mt = 0; mt < 4; mt++)
                a[mt] = *(const uint4*)(sA + ((mt * 64 + ks) * 32 + lane) * 4);
            #pragma unroll
            for (int mt = 0; mt < 4; mt++)
                #pragma unroll
                for (int nt = 0; nt < 8; nt++)
                    mma8(acc[mt][nt], a[mt], b0[nt]);
            if (ks < 62) {
                #pragma unroll
                for (int nt = 0; nt < 8; nt++)
                    b0[nt] = *(const float2*)(bbase + (nt * 64 + ks + 2) * 64 + lane * 2);
            }
            // odd half (reuse a)
            #pragma unroll
            for (int mt = 0; mt < 4; mt++)
                a[mt] = *(const uint4*)(sA + ((mt * 64 + ks + 1) * 32 + lane) * 4);
            #pragma unroll
            for (int mt = 0; mt < 4; mt++)
                #pragma unroll
                for (int nt = 0; nt < 8; nt++)
                    mma8(acc[mt][nt], a[mt], b1f[nt]);
            if (ks < 62) {
                #pragma unroll
                for (int nt = 0; nt < 8; nt++)
                    b1f[nt] = *(const float2*)(bbase + (nt * 64 + ks + 3) * 64 + lane * 2);
            }
        }
    }

    // ---- relu + b1, write h back into A region (fragment-major) ----
    __syncthreads();   // everyone done reading msg A
    #pragma unroll
    for (int mt = 0; mt < 4; mt++) {
        #pragma unroll
        for (int nt = 0; nt < 8; nt++) {
            #pragma unroll
            for (int cr = 0; cr < 4; cr++) {
                int row = mt * 16 + gid + 8 * (cr >> 1);
                int n   = warp * 64 + nt * 8 + 2 * tig + (cr & 1);
                float v = fmaxf(acc[mt][nt][cr] + s_b1[n], 0.0f);
                int r15 = row & 15;
                int ks  = n >> 3;
                int c0  = n & 7;
                int l2  = (r15 & 7) * 4 + (c0 & 3);
                int rg  = (r15 >> 3) + 2 * (c0 >> 2);
                sA[((mt * 64 + ks) * 32 + l2) * 4 + rg] =
                    __uint_as_float(f2tf32(v));
            }
        }
    }
    __syncthreads();

    // ---- GEMM2: out[64x256] = h @ W2 ; N-slice 32 per warp (copy-free) ----
    float acc2[4][4][4];
    #pragma unroll
    for (int mt = 0; mt < 4; mt++)
        #pragma unroll
        for (int nt = 0; nt < 4; nt++)
            #pragma unroll
            for (int r = 0; r < 4; r++) acc2[mt][nt][r] = 0.0f;

    {
        const float* bbase = g_W2F + (size_t)(warp * 4) * 4096;
        float2 b0[4], b1f[4];
        #pragma unroll
        for (int nt = 0; nt < 4; nt++) {
            b0[nt]  = *(const float2*)(bbase + (nt * 64 + 0) * 64 + lane * 2);
            b1f[nt] = *(const float2*)(bbase + (nt * 64 + 1) * 64 + lane * 2);
        }
        #pragma unroll 1
        for (int ks = 0; ks < 64; ks += 2) {
            uint4 a[4];
            // even half
            #pragma unroll
            for (int mt = 0; mt < 4; mt++)
                a[mt] = *(const uint4*)(sA + ((mt * 64 + ks) * 32 + lane) * 4);
            #pragma unroll
            for (int mt = 0; mt < 4; mt++)
                #pragma unroll
                for (int nt = 0; nt < 4; nt++)
                    mma8(acc2[mt][nt], a[mt], b0[nt]);
            if (ks < 62) {
                #pragma unroll
                for (int nt = 0; nt < 4; nt++)
                    b0[nt] = *(const float2*)(bbase + (nt * 64 + ks + 2) * 64 + lane * 2);
            }
            // odd half (reuse a)
            #pragma unroll
            for (int mt = 0; mt < 4; mt++)
                a[mt] = *(const uint4*)(sA + ((mt * 64 + ks + 1) * 32 + lane) * 4);
            #pragma unroll
            for (int mt = 0; mt < 4; mt++)
                #pragma unroll
                for (int nt = 0; nt < 4; nt++)
                    mma8(acc2[mt][nt], a[mt], b1f[nt]);
            if (ks < 62) {
                #pragma unroll
                for (int nt = 0; nt < 4; nt++)
                    b1f[nt] = *(const float2*)(bbase + (nt * 64 + ks + 3) * 64 + lane * 2);
            }
        }
    }

    // ---- epilogue: + b2, store ----
    #pragma unroll
    for (int mt = 0; mt < 4; mt++) {
        #pragma unroll
        for (int nt = 0; nt < 4; nt++) {
            int n  = warp * 32 + nt * 8 + 2 * tig;
            float bx = s_b2[n], by = s_b2[n + 1];
            int r0 = mt * 16 + gid;
            int e0 = base + r0;
            if (e0 < E) {
                float2 o;
                o.x = acc2[mt][nt][0] + bx;
                o.y = acc2[mt][nt][1] + by;
                *(float2*)(out + (size_t)e0 * 256 + n) = o;
            }
            int e1 = base + r0 + 8;
            if (e1 < E) {
                float2 o;
                o.x = acc2[mt][nt][2] + bx;
                o.y = acc2[mt][nt][3] + by;
                *(float2*)(out + (size_t)e1 * 256 + n) = o;
            }
        }
    }
}

// ------------------------------- launch ------------------------------------

extern "C" void kernel_launch(void* const* d_in, const int* in_sizes, int n_in,
                              void* d_out, int out_size) {
    const int*   src_nodes     = (const int*)d_in[0];
    const int*   dst_nodes     = (const int*)d_in[1];
    const float* timestamps    = (const float*)d_in[2];
    const int*   event_indices = (const int*)d_in[3];
    const int*   nidx          = (const int*)d_in[4];
    const float* node_emb      = (const float*)d_in[5];
    const float* last_update   = (const float*)d_in[6];
    const float* feats         = (const float*)d_in[7];
    const float* freq          = (const float*)d_in[8];
    const float* phase         = (const float*)d_in[9];
    const float* W1            = (const float*)d_in[10];
    const float* b1v           = (const float*)d_in[11];
    const float* W2            = (const float*)d_in[12];
    const float* b2v           = (const float*)d_in[13];
    float* out = (float*)d_out;

    int E = in_sizes[0];

    cudaFuncSetAttribute(tgn_msg_kernel,
                         cudaFuncAttributeMaxDynamicSharedMemorySize, SMEM_BYTES);

    prep_weights_kernel<<<128, 256>>>(W1, W2);

    int nblk = (E + E_TILE - 1) / E_TILE;
    tgn_msg_kernel<<<nblk, THREADS, SMEM_BYTES>>>(
        src_nodes, dst_nodes, timestamps, event_indices, nidx,
        node_emb, last_update, feats, freq, phase, b1v, b2v, out, E);
}